// round 12
// baseline (speedup 1.0000x reference)
#include <cuda_runtime.h>
#include <math.h>

#define Bv 32
#define Nv 512
#define Hv 128
#define NHv 8
#define HDv 16
#define FFv 512
#define NBINS 50
#define ROWS (Bv*Nv)   // 16384

typedef unsigned long long u64;

// ---------------- packed fp32x2 helpers (sm_103a FFMA2 path) ----------------
__device__ __forceinline__ u64 pack2(float x, float y){
    u64 r; asm("mov.b64 %0, {%1, %2};" : "=l"(r) : "f"(x), "f"(y)); return r;
}
__device__ __forceinline__ void unpack2(u64 v, float& x, float& y){
    asm("mov.b64 {%0, %1}, %2;" : "=f"(x), "=f"(y) : "l"(v));
}
__device__ __forceinline__ void fma2(u64& c, u64 a, u64 b){
    asm("fma.rn.f32x2 %0, %1, %2, %3;" : "=l"(c) : "l"(a), "l"(b), "l"(c));
}
__device__ __forceinline__ u64 mul2(u64 a, u64 b){
    u64 r; asm("mul.rn.f32x2 %0, %1, %2;" : "=l"(r) : "l"(a), "l"(b)); return r;
}

// ---------------- scratch (no allocations allowed) ----------------
__device__ float g_hn[ROWS*Hv];
__device__ float g_q [ROWS*Hv];
__device__ float g_k [ROWS*Hv];
__device__ float g_v [ROWS*Hv];
__device__ float g_ao[ROWS*Hv];
__device__ float g_u [ROWS*2*FFv];
__device__ unsigned char g_bins[(size_t)ROWS*Nv];   // 8.4 MB, fits L2

// ---------------- distance->bin precompute (once per launch) ----------------
__global__ __launch_bounds__(256) void bins_kernel(
    const float* __restrict__ dist, unsigned char* __restrict__ bins)
{
    int i = (blockIdx.x*256 + threadIdx.x) * 4;
    float4 d = *(const float4*)(dist + i);
    int b0 = (int)(d.x*10.f); b0 = b0<0?0:(b0>NBINS-1?NBINS-1:b0);
    int b1 = (int)(d.y*10.f); b1 = b1<0?0:(b1>NBINS-1?NBINS-1:b1);
    int b2 = (int)(d.z*10.f); b2 = b2<0?0:(b2>NBINS-1?NBINS-1:b2);
    int b3 = (int)(d.w*10.f); b3 = b3<0?0:(b3>NBINS-1?NBINS-1:b3);
    uchar4 o; o.x=(unsigned char)b0; o.y=(unsigned char)b1;
    o.z=(unsigned char)b2; o.w=(unsigned char)b3;
    *(uchar4*)(bins + i) = o;
}

// ---------------- LayerNorm: one warp per 128-wide row ----------------
__global__ __launch_bounds__(256) void ln_kernel(
    const float* __restrict__ h,
    const float* __restrict__ gamma,
    const float* __restrict__ beta,
    float* __restrict__ out)
{
    int row  = blockIdx.x * 8 + (threadIdx.x >> 5);
    int lane = threadIdx.x & 31;
    const float4* hp = (const float4*)(h + (size_t)row * Hv);
    float4 v = hp[lane];
    float s  = v.x + v.y + v.z + v.w;
    float ss = v.x*v.x + v.y*v.y + v.z*v.z + v.w*v.w;
    #pragma unroll
    for (int off = 16; off; off >>= 1) {
        s  += __shfl_xor_sync(0xffffffffu, s,  off);
        ss += __shfl_xor_sync(0xffffffffu, ss, off);
    }
    float mu  = s * (1.0f/Hv);
    float var = ss * (1.0f/Hv) - mu*mu;
    float inv = rsqrtf(var + 1e-5f);
    float4 g4 = ((const float4*)gamma)[lane];
    float4 b4 = ((const float4*)beta)[lane];
    float4 o;
    o.x = (v.x-mu)*inv*g4.x + b4.x;
    o.y = (v.y-mu)*inv*g4.y + b4.y;
    o.z = (v.z-mu)*inv*g4.z + b4.z;
    o.w = (v.w-mu)*inv*g4.w + b4.w;
    ((float4*)(out + (size_t)row*Hv))[lane] = o;
}

// ---------------- SGEMM: TMx128 tile, BK=16, f32x2 FMA ----
// MODE: 0 = plain, 1 = +residual, 2 = GLU(A)+residual, 3 = fused QKV (3 W/b/C)
// TM: 128 (8x8 micro) or 64 (4x8 micro, doubles grid for small-N launches)
template<int MODE, int TM>
__global__ __launch_bounds__(256) void gemm_kernel(
    const float* __restrict__ A,
    const float* __restrict__ W0, const float* __restrict__ B0, float* __restrict__ C0,
    const float* __restrict__ W1, const float* __restrict__ B1c, float* __restrict__ C1,
    const float* __restrict__ W2, const float* __restrict__ B2c, float* __restrict__ C2,
    const float* __restrict__ R, int K, int Nc)
{
    constexpr int MR  = TM/16;                 // micro rows per thread
    constexpr int AP  = (TM==128) ? 132 : 68;  // padded As row stride
    constexpr int NLD = (TM==128) ? 2 : 1;     // float4 A-loads per thread
    __shared__ __align__(16) float As[2][16][AP];
    __shared__ __align__(16) float Ws[2][16][128];
    const int tid = threadIdx.x;
    const float *W, *bias; float* C;
    int bn;
    if (MODE == 3) {
        int s = blockIdx.x;
        W    = (s==0)?W0:((s==1)?W1:W2);
        bias = (s==0)?B0:((s==1)?B1c:B2c);
        C    = (s==0)?C0:((s==1)?C1:C2);
        bn = 0;
    } else { W = W0; bias = B0; C = C0; bn = blockIdx.x * 128; }
    const int bm = blockIdx.y * TM;
    const int tx = tid & 15, ty = tid >> 4;
    const int ar = (TM==128) ? (tid>>1) : (tid>>2);
    const int ac = (TM==128) ? ((tid&1)*8) : ((tid&3)*4);
    const int wr = tid >> 4, wc = (tid & 15) * 8;
    const int ldA = (MODE==2) ? (2*FFv) : K;
    const float* Arow = A + (size_t)(bm + ar) * ldA;
    const float* Wp   = W + (size_t)wr * Nc + bn + wc;

    u64 acc[MR][4];
    #pragma unroll
    for (int i=0;i<MR;i++)
        #pragma unroll
        for (int j=0;j<4;j++) acc[i][j] = 0ull;

    float4 av[NLD], wv0, wv1;
    auto LOADT = [&](int k0){
        #pragma unroll
        for (int n=0;n<NLD;n++){
            if (MODE==2){
                float4 pp = *(const float4*)(Arow + k0 + ac + 4*n);
                float4 ss = *(const float4*)(Arow + FFv + k0 + ac + 4*n);
                av[n].x = pp.x/(1.f+__expf(-ss.x));
                av[n].y = pp.y/(1.f+__expf(-ss.y));
                av[n].z = pp.z/(1.f+__expf(-ss.z));
                av[n].w = pp.w/(1.f+__expf(-ss.w));
            } else {
                av[n] = *(const float4*)(Arow + k0 + ac + 4*n);
            }
        }
        wv0 = *(const float4*)(Wp + (size_t)k0*Nc);
        wv1 = *(const float4*)(Wp + (size_t)k0*Nc + 4);
    };
    auto STORET = [&](int b){
        #pragma unroll
        for (int n=0;n<NLD;n++){
            As[b][ac+4*n+0][ar]=av[n].x; As[b][ac+4*n+1][ar]=av[n].y;
            As[b][ac+4*n+2][ar]=av[n].z; As[b][ac+4*n+3][ar]=av[n].w;
        }
        *(float4*)&Ws[b][wr][wc]   = wv0;
        *(float4*)&Ws[b][wr][wc+4] = wv1;
    };

    LOADT(0); STORET(0); __syncthreads();
    const int nt = K/16;
    for (int t = 0; t < nt; t++) {
        int cur = t & 1;
        if (t+1 < nt) LOADT((t+1)*16);
        #pragma unroll
        for (int kk = 0; kk < 16; kk++) {
            float av2[MR];
            #pragma unroll
            for (int j=0;j<MR;j+=4)
                *(float4*)&av2[j] = *(float4*)&As[cur][kk][ty*MR + j];
            const u64* bp = (const u64*)&Ws[cur][kk][tx*8];
            u64 b2[4]; b2[0]=bp[0]; b2[1]=bp[1]; b2[2]=bp[2]; b2[3]=bp[3];
            #pragma unroll
            for (int i=0;i<MR;i++){
                u64 a2 = pack2(av2[i], av2[i]);
                #pragma unroll
                for (int j=0;j<4;j++) fma2(acc[i][j], a2, b2[j]);
            }
        }
        if (t+1 < nt) STORET(cur^1);
        __syncthreads();
    }

    const int cn = bn + tx*8;
    float4 bv0 = *(const float4*)(bias + cn);
    float4 bv1 = *(const float4*)(bias + cn + 4);
    #pragma unroll
    for (int i = 0; i < MR; i++) {
        int cm = bm + ty*MR + i;
        float c[8];
        #pragma unroll
        for (int j=0;j<4;j++) unpack2(acc[i][j], c[2*j], c[2*j+1]);
        c[0]+=bv0.x; c[1]+=bv0.y; c[2]+=bv0.z; c[3]+=bv0.w;
        c[4]+=bv1.x; c[5]+=bv1.y; c[6]+=bv1.z; c[7]+=bv1.w;
        if (MODE==1 || MODE==2) {
            float4 r0 = *(const float4*)(R + (size_t)cm*Nc + cn);
            float4 r1 = *(const float4*)(R + (size_t)cm*Nc + cn + 4);
            c[0]+=r0.x; c[1]+=r0.y; c[2]+=r0.z; c[3]+=r0.w;
            c[4]+=r1.x; c[5]+=r1.y; c[6]+=r1.z; c[7]+=r1.w;
        }
        float4 o0 = make_float4(c[0],c[1],c[2],c[3]);
        float4 o1 = make_float4(c[4],c[5],c[6],c[7]);
        *(float4*)(C + (size_t)cm*Nc + cn)     = o0;
        *(float4*)(C + (size_t)cm*Nc + cn + 4) = o1;
    }
}

// ---------------- fused attention v2.2 (v2 + fused per-warp combine) --------
// Block: (b, head, 64-query tile), 256 threads, KT=128 key tiles.
// Warp w: row group (w>>1, 16 rows), key half h=w&1 (64 keys).
// Lane: 16 rows x 2 keys scores in registers.
// Running softmax stats DOUBLE-BUFFERED in smem: each tile reads slot kt&1,
// h==0 warp writes slot (kt&1)^1 — no RMW race, no serialized combine pass.
// PV: 2q x 2d blocking, u64 (LDS.64) over keys; VP=134 => conflict-free V rows.
#define QT2 64
#define KT2 128
#define QP 18
#define KP2 18
#define VP 134
#define SP2 132

#define SM_QS   0
#define SM_KS   (SM_QS + QT2*QP)        // 1152
#define SM_VT   (SM_KS + KT2*KP2)       // +2304
#define SM_P    (SM_VT + HDv*VP)        // +2144
#define SM_PM   (SM_P  + QT2*SP2)       // +8448
#define SM_PS   (SM_PM + 2*QT2)
#define SM_RM2  (SM_PS + 2*QT2)         // 2*QT2 (double-buffered row max)
#define SM_RL2  (SM_RM2 + 2*QT2)        // 2*QT2 (double-buffered row sum)
#define SM_RS   (SM_RL2 + 2*QT2)        // per-tile rescale factor
#define SM_DB   (SM_RS + QT2)
#define SM_MASK (SM_DB + 64)
#define ATTN_SMEM_FLOATS (SM_MASK + KT2)
#define ATTN_SMEM_BYTES  (ATTN_SMEM_FLOATS*4)

__global__ __launch_bounds__(256) void attn_kernel(
    const float* __restrict__ Q, const float* __restrict__ Kg,
    const float* __restrict__ V, const unsigned char* __restrict__ bins,
    const int* __restrict__ mask,
    const float* __restrict__ demb, const float* __restrict__ abias,
    float* __restrict__ AO)
{
    extern __shared__ __align__(16) float sm[];
    float* Qs = sm + SM_QS;
    float* Ks = sm + SM_KS;
    float* Vt = sm + SM_VT;
    float* P  = sm + SM_P;
    float* pm = sm + SM_PM;
    float* ps = sm + SM_PS;
    float* rowm2 = sm + SM_RM2;
    float* rowl2 = sm + SM_RL2;
    float* rsc   = sm + SM_RS;
    float* db    = sm + SM_DB;
    int*  maskt  = (int*)(sm + SM_MASK);

    const int tid = threadIdx.x;
    const int qt = blockIdx.x, hh = blockIdx.y, bb = blockIdx.z;
    const int q0g = bb*Nv + qt*QT2;

    if (tid < NBINS) db[tid] = demb[tid*NHv + hh];
    if (tid < QT2) { rowm2[tid] = -1e30f; rowl2[tid] = 0.f; }  // slot 0 init
    {   // load Q tile [64 x 16]
        int r = tid >> 2, j = (tid & 3) << 2;
        float4 qv = *(const float4*)(Q + (size_t)(q0g + r)*Hv + hh*HDv + j);
        float* dst = &Qs[r*QP + j];
        *(float2*)dst     = make_float2(qv.x, qv.y);
        *(float2*)(dst+2) = make_float2(qv.z, qv.w);
    }
    __syncthreads();

    const float ab = abias[hh];
    const int w = tid >> 5, lane = tid & 31;
    const int rowbase = (w >> 1) * 16;   // 0,16,32,48
    const int h = w & 1;
    const int k0l = 64*h + lane, k1l = k0l + 32;

    // PV mapping: 4 outputs/thread (rows qp, qp+32; dims 2dp, 2dp+1)
    const int qp = tid >> 3, dp = tid & 7;
    u64 a00 = 0ull, a01 = 0ull, a10 = 0ull, a11 = 0ull;

    float t0[16], t1[16];

    for (int kt = 0; kt < Nv/KT2; kt++) {
        const int kb = kt*KT2;
        const int s = kt & 1;
        __syncthreads();   // guard all tiles vs previous iteration consumers
        // --- load K (row-major) / V (transposed) tiles: 128 x 16 each ---
        #pragma unroll
        for (int ii = 0; ii < 2; ii++) {
            int id = tid + ii*256;
            int r = id >> 2, j = (id & 3) << 2;
            size_t goff = (size_t)(bb*Nv + kb + r)*Hv + hh*HDv + j;
            float4 kv = *(const float4*)(Kg + goff);
            float* kd = &Ks[r*KP2 + j];
            *(float2*)kd     = make_float2(kv.x, kv.y);
            *(float2*)(kd+2) = make_float2(kv.z, kv.w);
            float4 vv = *(const float4*)(V + goff);
            Vt[(j+0)*VP + r] = vv.x;
            Vt[(j+1)*VP + r] = vv.y;
            Vt[(j+2)*VP + r] = vv.z;
            Vt[(j+3)*VP + r] = vv.w;
        }
        if (tid < KT2) maskt[tid] = mask[bb*Nv + kb + tid];
        __syncthreads();

        // --- scores: 16 rows x 2 keys per lane ---
        u64 kr0[8], kr1[8];
        {
            const u64* p0 = (const u64*)&Ks[k0l*KP2];
            const u64* p1 = (const u64*)&Ks[k1l*KP2];
            #pragma unroll
            for (int d=0; d<8; d++) { kr0[d]=p0[d]; kr1[d]=p1[d]; }
        }
        const bool m0 = (maskt[k0l] != 0), m1 = (maskt[k1l] != 0);
        #pragma unroll
        for (int r = 0; r < 16; r++) {
            const u64* qr = (const u64*)&Qs[(rowbase + r)*QP];
            u64 s0p = 0ull, s1p = 0ull;
            #pragma unroll
            for (int d=0; d<8; d++) {
                u64 qd = qr[d];
                fma2(s0p, qd, kr0[d]);
                fma2(s1p, qd, kr1[d]);
            }
            float e, o;
            unpack2(s0p, e, o); float s0 = (e+o)*0.25f;
            unpack2(s1p, e, o); float s1 = (e+o)*0.25f;
            const unsigned char* brow = bins + (size_t)(q0g + rowbase + r)*Nv + kb;
            s0 = m0 ? -1e9f : (s0 + db[brow[k0l]] + ab);
            s1 = m1 ? -1e9f : (s1 + db[brow[k1l]] + ab);
            t0[r] = s0; t1[r] = s1;
        }
        // --- per-warp-half stats (max + sum of exp) ---
        #pragma unroll
        for (int r = 0; r < 16; r++) {
            float m = fmaxf(t0[r], t1[r]);
            #pragma unroll
            for (int off=16; off; off>>=1)
                m = fmaxf(m, __shfl_xor_sync(0xffffffffu, m, off));
            float e0 = __expf(t0[r] - m);
            float e1 = __expf(t1[r] - m);
            t0[r] = e0; t1[r] = e1;
            float sum = e0 + e1;
            #pragma unroll
            for (int off=16; off; off>>=1)
                sum += __shfl_xor_sync(0xffffffffu, sum, off);
            if (lane == 0) {
                pm[h*QT2 + rowbase + r] = m;
                ps[h*QT2 + rowbase + r] = sum;
            }
        }
        __syncthreads();
        // --- fused combine (per-warp, redundant across halves) + P write ---
        // Reads stats slot s; h==0 warp writes slot s^1 (no RMW race).
        #pragma unroll
        for (int r = 0; r < 16; r++) {
            int row = rowbase + r;
            float mA = pm[row], mB = pm[QT2 + row];
            float oldm = rowm2[s*QT2 + row];
            float nm = fmaxf(oldm, fmaxf(mA, mB));
            float sH = __expf((h ? mB : mA) - nm);
            if (h == 0) {
                float so = __expf(oldm - nm);
                rowm2[(s^1)*QT2 + row] = nm;
                rowl2[(s^1)*QT2 + row] = rowl2[s*QT2 + row]*so
                    + ps[row]*__expf(mA - nm) + ps[QT2 + row]*__expf(mB - nm);
                rsc[row] = so;
            }
            P[row*SP2 + k0l] = t0[r]*sH;
            P[row*SP2 + k1l] = t1[r]*sH;
        }
        __syncthreads();
        // --- PV: rescale accs, then accumulate this tile ---
        {
            u64 r0p = pack2(rsc[qp],    rsc[qp]);
            u64 r1p = pack2(rsc[qp+32], rsc[qp+32]);
            a00 = mul2(a00, r0p); a01 = mul2(a01, r0p);
            a10 = mul2(a10, r1p); a11 = mul2(a11, r1p);
            const u64* p0 = (const u64*)&P[qp*SP2];
            const u64* p1 = (const u64*)&P[(qp+32)*SP2];
            const u64* v0 = (const u64*)&Vt[(2*dp  )*VP];
            const u64* v1 = (const u64*)&Vt[(2*dp+1)*VP];
            #pragma unroll 8
            for (int k2 = 0; k2 < KT2/2; k2++) {
                u64 pa = p0[k2], pb = p1[k2];
                u64 va = v0[k2], vb = v1[k2];
                fma2(a00, pa, va); fma2(a01, pa, vb);
                fma2(a10, pb, va); fma2(a11, pb, vb);
            }
        }
    }
    // --- epilogue (Nv/KT2 = 4 tiles -> final stats live in slot 0) ---
    float inv0 = 1.0f / rowl2[qp];
    float inv1 = 1.0f / rowl2[qp+32];
    float e, o;
    float* out0 = AO + (size_t)(q0g + qp)*Hv + hh*HDv + 2*dp;
    float* out1 = AO + (size_t)(q0g + qp + 32)*Hv + hh*HDv + 2*dp;
    unpack2(a00, e, o); float o00 = (e+o)*inv0;
    unpack2(a01, e, o); float o01 = (e+o)*inv0;
    unpack2(a10, e, o); float o10 = (e+o)*inv1;
    unpack2(a11, e, o); float o11 = (e+o)*inv1;
    *(float2*)out0 = make_float2(o00, o01);
    *(float2*)out1 = make_float2(o10, o11);
}

// ---------------- launch ----------------
extern "C" void kernel_launch(void* const* d_in, const int* in_sizes, int n_in,
                              void* d_out, int out_size)
{
    const float* x    = (const float*)d_in[0];
    const float* dist = (const float*)d_in[1];
    const int*   mask = (const int*)d_in[2];
    const float* Wq  = (const float*)d_in[3];
    const float* bq  = (const float*)d_in[4];
    const float* Wk  = (const float*)d_in[5];
    const float* bk  = (const float*)d_in[6];
    const float* Wv  = (const float*)d_in[7];
    const float* bv  = (const float*)d_in[8];
    const float* Wo  = (const float*)d_in[9];
    const float* bo  = (const float*)d_in[10];
    const float* demb= (const float*)d_in[11];
    const float* ab  = (const float*)d_in[12];
    const float* g1  = (const float*)d_in[13];
    const float* b1  = (const float*)d_in[14];
    const float* g2  = (const float*)d_in[15];
    const float* b2  = (const float*)d_in[16];
    const float* Wf1 = (const float*)d_in[17];
    const float* bf1 = (const float*)d_in[18];
    const float* Wf2 = (const float*)d_in[19];
    const float* bf2 = (const float*)d_in[20];

    float* h = (float*)d_out;
    float *hn, *q, *k, *v, *ao, *u;
    unsigned char* bins;
    cudaGetSymbolAddress((void**)&hn, g_hn);
    cudaGetSymbolAddress((void**)&q,  g_q);
    cudaGetSymbolAddress((void**)&k,  g_k);
    cudaGetSymbolAddress((void**)&v,  g_v);
    cudaGetSymbolAddress((void**)&ao, g_ao);
    cudaGetSymbolAddress((void**)&u,  g_u);
    cudaGetSymbolAddress((void**)&bins, g_bins);

    cudaFuncSetAttribute(attn_kernel,
        cudaFuncAttributeMaxDynamicSharedMemorySize, ATTN_SMEM_BYTES);

    cudaMemcpyAsync(h, x, (size_t)ROWS*Hv*sizeof(float), cudaMemcpyDeviceToDevice);
    bins_kernel<<<(ROWS*Nv)/1024, 256>>>(dist, bins);

    dim3 gqkv(3, ROWS/128);          // fused QKV (384 blocks)
    dim3 gone64(1, ROWS/64);         // N=128 GEMMs, TM=64 (256 blocks)
    dim3 gff1(2*FFv/128, ROWS/128);  // (8, 128)
    dim3 gattn(Nv/QT2, NHv, Bv);     // (8, 8, 32)

    for (int l = 0; l < 3; l++) {
        ln_kernel<<<ROWS/8, 256>>>(h, g1 + l*Hv, b1 + l*Hv, hn);
        gemm_kernel<3,128><<<gqkv, 256>>>(hn,
            Wq + (size_t)l*Hv*Hv, bq + l*Hv, q,
            Wk + (size_t)l*Hv*Hv, bk + l*Hv, k,
            Wv + (size_t)l*Hv*Hv, bv + l*Hv, v,
            nullptr, Hv, Hv);
        attn_kernel<<<gattn, 256, ATTN_SMEM_BYTES>>>(q, k, v, bins, mask,
                                    demb + (size_t)l*NBINS*NHv, ab + l*NHv, ao);
        gemm_kernel<1,64><<<gone64, 256>>>(ao,
            Wo + (size_t)l*Hv*Hv, bo + l*Hv, h,
            nullptr, nullptr, nullptr, nullptr, nullptr, nullptr,
            h, Hv, Hv);
        ln_kernel<<<ROWS/8, 256>>>(h, g2 + l*Hv, b2 + l*Hv, hn);
        gemm_kernel<0,128><<<gff1, 256>>>(hn,
            Wf1 + (size_t)l*Hv*2*FFv, bf1 + (size_t)l*2*FFv, u,
            nullptr, nullptr, nullptr, nullptr, nullptr, nullptr,
            nullptr, Hv, 2*FFv);
        gemm_kernel<2,64><<<gone64, 256>>>(u,
            Wf2 + (size_t)l*FFv*Hv, bf2 + l*Hv, h,
            nullptr, nullptr, nullptr, nullptr, nullptr, nullptr,
            h, FFv, Hv);
    }
}

// round 13
// speedup vs baseline: 1.1260x; 1.1260x over previous
#include <cuda_runtime.h>
#include <math.h>

#define Bv 32
#define Nv 512
#define Hv 128
#define NHv 8
#define HDv 16
#define FFv 512
#define NBINS 50
#define ROWS (Bv*Nv)   // 16384

typedef unsigned long long u64;

// ---------------- packed fp32x2 helpers (sm_103a FFMA2 path) ----------------
__device__ __forceinline__ u64 pack2(float x, float y){
    u64 r; asm("mov.b64 %0, {%1, %2};" : "=l"(r) : "f"(x), "f"(y)); return r;
}
__device__ __forceinline__ void unpack2(u64 v, float& x, float& y){
    asm("mov.b64 {%0, %1}, %2;" : "=f"(x), "=f"(y) : "l"(v));
}
__device__ __forceinline__ void fma2(u64& c, u64 a, u64 b){
    asm("fma.rn.f32x2 %0, %1, %2, %3;" : "=l"(c) : "l"(a), "l"(b), "l"(c));
}
__device__ __forceinline__ u64 mul2(u64 a, u64 b){
    u64 r; asm("mul.rn.f32x2 %0, %1, %2;" : "=l"(r) : "l"(a), "l"(b)); return r;
}

// ---------------- scratch (no allocations allowed) ----------------
__device__ float g_hn[ROWS*Hv];
__device__ float g_q [ROWS*Hv];
__device__ float g_k [ROWS*Hv];
__device__ float g_v [ROWS*Hv];
__device__ float g_ao[ROWS*Hv];
__device__ float g_u [ROWS*2*FFv];
__device__ unsigned char g_bins[(size_t)ROWS*Nv];   // 8.4 MB, fits L2

// ---------------- distance->bin precompute (once per launch) ----------------
__global__ __launch_bounds__(256) void bins_kernel(
    const float* __restrict__ dist, unsigned char* __restrict__ bins)
{
    int i = (blockIdx.x*256 + threadIdx.x) * 4;
    float4 d = *(const float4*)(dist + i);
    int b0 = (int)(d.x*10.f); b0 = b0<0?0:(b0>NBINS-1?NBINS-1:b0);
    int b1 = (int)(d.y*10.f); b1 = b1<0?0:(b1>NBINS-1?NBINS-1:b1);
    int b2 = (int)(d.z*10.f); b2 = b2<0?0:(b2>NBINS-1?NBINS-1:b2);
    int b3 = (int)(d.w*10.f); b3 = b3<0?0:(b3>NBINS-1?NBINS-1:b3);
    uchar4 o; o.x=(unsigned char)b0; o.y=(unsigned char)b1;
    o.z=(unsigned char)b2; o.w=(unsigned char)b3;
    *(uchar4*)(bins + i) = o;
}

// ---------------- LayerNorm: one warp per 128-wide row ----------------
__global__ __launch_bounds__(256) void ln_kernel(
    const float* __restrict__ h,
    const float* __restrict__ gamma,
    const float* __restrict__ beta,
    float* __restrict__ out)
{
    int row  = blockIdx.x * 8 + (threadIdx.x >> 5);
    int lane = threadIdx.x & 31;
    const float4* hp = (const float4*)(h + (size_t)row * Hv);
    float4 v = hp[lane];
    float s  = v.x + v.y + v.z + v.w;
    float ss = v.x*v.x + v.y*v.y + v.z*v.z + v.w*v.w;
    #pragma unroll
    for (int off = 16; off; off >>= 1) {
        s  += __shfl_xor_sync(0xffffffffu, s,  off);
        ss += __shfl_xor_sync(0xffffffffu, ss, off);
    }
    float mu  = s * (1.0f/Hv);
    float var = ss * (1.0f/Hv) - mu*mu;
    float inv = rsqrtf(var + 1e-5f);
    float4 g4 = ((const float4*)gamma)[lane];
    float4 b4 = ((const float4*)beta)[lane];
    float4 o;
    o.x = (v.x-mu)*inv*g4.x + b4.x;
    o.y = (v.y-mu)*inv*g4.y + b4.y;
    o.z = (v.z-mu)*inv*g4.z + b4.z;
    o.w = (v.w-mu)*inv*g4.w + b4.w;
    ((float4*)(out + (size_t)row*Hv))[lane] = o;
}

// ---------------- SGEMM: 128x128 tile, BK=16, 8x8 micro-tile, f32x2 FMA ----
// MODE: 0 = plain, 1 = +residual, 2 = GLU(A)+residual, 3 = fused QKV (3 W/b/C)
template<int MODE>
__global__ __launch_bounds__(256) void gemm_kernel(
    const float* __restrict__ A,
    const float* __restrict__ W0, const float* __restrict__ B0, float* __restrict__ C0,
    const float* __restrict__ W1, const float* __restrict__ B1c, float* __restrict__ C1,
    const float* __restrict__ W2, const float* __restrict__ B2c, float* __restrict__ C2,
    const float* __restrict__ R, int K, int Nc)
{
    __shared__ __align__(16) float As[2][16][132];
    __shared__ __align__(16) float Ws[2][16][128];
    const int tid = threadIdx.x;
    const float *W, *bias; float* C;
    int bn;
    if (MODE == 3) {
        int s = blockIdx.x;
        W    = (s==0)?W0:((s==1)?W1:W2);
        bias = (s==0)?B0:((s==1)?B1c:B2c);
        C    = (s==0)?C0:((s==1)?C1:C2);
        bn = 0;
    } else { W = W0; bias = B0; C = C0; bn = blockIdx.x * 128; }
    const int bm = blockIdx.y * 128;
    const int tx = tid & 15, ty = tid >> 4;
    const int ar = tid >> 1, ac = (tid & 1) * 8;   // A loader: row ar, 8 cols
    const int wr = tid >> 4, wc = (tid & 15) * 8;  // W loader: row wr, 8 cols
    const int ldA = (MODE==2) ? (2*FFv) : K;
    const float* Arow = A + (size_t)(bm + ar) * ldA;
    const float* Wp   = W + (size_t)wr * Nc + bn + wc;

    u64 acc[8][4];
    #pragma unroll
    for (int i=0;i<8;i++)
        #pragma unroll
        for (int j=0;j<4;j++) acc[i][j] = 0ull;

    float4 a0v, a1v, w0v, w1v;
    #define LOADT(k0) do { \
        if (MODE==2) { \
            float4 p0 = *(const float4*)(Arow + (k0) + ac); \
            float4 p1 = *(const float4*)(Arow + (k0) + ac + 4); \
            float4 s0 = *(const float4*)(Arow + FFv + (k0) + ac); \
            float4 s1 = *(const float4*)(Arow + FFv + (k0) + ac + 4); \
            a0v.x = p0.x/(1.f+__expf(-s0.x)); a0v.y = p0.y/(1.f+__expf(-s0.y)); \
            a0v.z = p0.z/(1.f+__expf(-s0.z)); a0v.w = p0.w/(1.f+__expf(-s0.w)); \
            a1v.x = p1.x/(1.f+__expf(-s1.x)); a1v.y = p1.y/(1.f+__expf(-s1.y)); \
            a1v.z = p1.z/(1.f+__expf(-s1.z)); a1v.w = p1.w/(1.f+__expf(-s1.w)); \
        } else { \
            a0v = *(const float4*)(Arow + (k0) + ac); \
            a1v = *(const float4*)(Arow + (k0) + ac + 4); \
        } \
        w0v = *(const float4*)(Wp + (size_t)(k0)*Nc); \
        w1v = *(const float4*)(Wp + (size_t)(k0)*Nc + 4); \
    } while(0)
    #define STORET(b) do { \
        As[b][ac+0][ar]=a0v.x; As[b][ac+1][ar]=a0v.y; \
        As[b][ac+2][ar]=a0v.z; As[b][ac+3][ar]=a0v.w; \
        As[b][ac+4][ar]=a1v.x; As[b][ac+5][ar]=a1v.y; \
        As[b][ac+6][ar]=a1v.z; As[b][ac+7][ar]=a1v.w; \
        *(float4*)&Ws[b][wr][wc]   = w0v; \
        *(float4*)&Ws[b][wr][wc+4] = w1v; \
    } while(0)

    LOADT(0); STORET(0); __syncthreads();
    const int nt = K/16;
    for (int t = 0; t < nt; t++) {
        int cur = t & 1;
        if (t+1 < nt) LOADT((t+1)*16);
        #pragma unroll
        for (int kk = 0; kk < 16; kk++) {
            float4 af0 = *(float4*)&As[cur][kk][ty*8];
            float4 af1 = *(float4*)&As[cur][kk][ty*8+4];
            const u64* bp = (const u64*)&Ws[cur][kk][tx*8];
            u64 b2[4]; b2[0]=bp[0]; b2[1]=bp[1]; b2[2]=bp[2]; b2[3]=bp[3];
            u64 as2[8];
            as2[0]=pack2(af0.x,af0.x); as2[1]=pack2(af0.y,af0.y);
            as2[2]=pack2(af0.z,af0.z); as2[3]=pack2(af0.w,af0.w);
            as2[4]=pack2(af1.x,af1.x); as2[5]=pack2(af1.y,af1.y);
            as2[6]=pack2(af1.z,af1.z); as2[7]=pack2(af1.w,af1.w);
            #pragma unroll
            for (int i=0;i<8;i++)
                #pragma unroll
                for (int j=0;j<4;j++) fma2(acc[i][j], as2[i], b2[j]);
        }
        if (t+1 < nt) STORET(cur^1);
        __syncthreads();
    }
    #undef LOADT
    #undef STORET

    const int cn = bn + tx*8;
    float4 bv0 = *(const float4*)(bias + cn);
    float4 bv1 = *(const float4*)(bias + cn + 4);
    #pragma unroll
    for (int i = 0; i < 8; i++) {
        int cm = bm + ty*8 + i;
        float c[8];
        #pragma unroll
        for (int j=0;j<4;j++) unpack2(acc[i][j], c[2*j], c[2*j+1]);
        c[0]+=bv0.x; c[1]+=bv0.y; c[2]+=bv0.z; c[3]+=bv0.w;
        c[4]+=bv1.x; c[5]+=bv1.y; c[6]+=bv1.z; c[7]+=bv1.w;
        if (MODE==1 || MODE==2) {
            float4 r0 = *(const float4*)(R + (size_t)cm*Nc + cn);
            float4 r1 = *(const float4*)(R + (size_t)cm*Nc + cn + 4);
            c[0]+=r0.x; c[1]+=r0.y; c[2]+=r0.z; c[3]+=r0.w;
            c[4]+=r1.x; c[5]+=r1.y; c[6]+=r1.z; c[7]+=r1.w;
        }
        float4 o0 = make_float4(c[0],c[1],c[2],c[3]);
        float4 o1 = make_float4(c[4],c[5],c[6],c[7]);
        *(float4*)(C + (size_t)cm*Nc + cn)     = o0;
        *(float4*)(C + (size_t)cm*Nc + cn + 4) = o1;
    }
}

// ---------------- fused attention v2.3 (R6 v2 + float4 Q-row loads) ---------
// Block: (b, head, 64-query tile), 256 threads, KT=128 key tiles.
// Warp w: row group g=w>>1 (16 rows), key half h=w&1 (64 keys).
// Lane: 16 rows x 2 keys scores in registers.
// Single-pass softmax (register partials + tiny smem combine); P written once.
// PV: 2q x 2d blocking, u64 loads over keys (VP=134: conflict-free V rows).
// QP=20 -> Qs rows 16B-aligned, score-phase Q reads are 4x LDS.128 broadcast.
#define QT2 64
#define KT2 128
#define QP 20
#define KP2 18
#define VP 134
#define SP2 132

#define SM_QS   0
#define SM_KS   (SM_QS + QT2*QP)        // 1280
#define SM_VT   (SM_KS + KT2*KP2)       // +2304
#define SM_P    (SM_VT + HDv*VP)        // +2144
#define SM_PM   (SM_P  + QT2*SP2)       // +8448
#define SM_PS   (SM_PM + 2*QT2)
#define SM_RM   (SM_PS + 2*QT2)
#define SM_RL   (SM_RM + QT2)
#define SM_RS   (SM_RL + QT2)
#define SM_SC0  (SM_RS + QT2)
#define SM_SC1  (SM_SC0 + QT2)
#define SM_DB   (SM_SC1 + QT2)
#define SM_MASK (SM_DB + 64)
#define ATTN_SMEM_FLOATS (SM_MASK + KT2)
#define ATTN_SMEM_BYTES  (ATTN_SMEM_FLOATS*4)

__global__ __launch_bounds__(256) void attn_kernel(
    const float* __restrict__ Q, const float* __restrict__ Kg,
    const float* __restrict__ V, const unsigned char* __restrict__ bins,
    const int* __restrict__ mask,
    const float* __restrict__ demb, const float* __restrict__ abias,
    float* __restrict__ AO)
{
    extern __shared__ __align__(16) float sm[];
    float* Qs = sm + SM_QS;
    float* Ks = sm + SM_KS;
    float* Vt = sm + SM_VT;
    float* P  = sm + SM_P;
    float* pm = sm + SM_PM;
    float* ps = sm + SM_PS;
    float* rowm = sm + SM_RM;
    float* rowl = sm + SM_RL;
    float* rsc  = sm + SM_RS;
    float* sc0  = sm + SM_SC0;
    float* sc1  = sm + SM_SC1;
    float* db   = sm + SM_DB;
    int*  maskt = (int*)(sm + SM_MASK);

    const int tid = threadIdx.x;
    const int qt = blockIdx.x, hh = blockIdx.y, bb = blockIdx.z;
    const int q0g = bb*Nv + qt*QT2;

    if (tid < NBINS) db[tid] = demb[tid*NHv + hh];
    if (tid < QT2) { rowm[tid] = -1e30f; rowl[tid] = 0.f; }
    {   // load Q tile [64 x 16] (QP=20: float4-aligned rows)
        int r = tid >> 2, j = (tid & 3) << 2;
        float4 qv = *(const float4*)(Q + (size_t)(q0g + r)*Hv + hh*HDv + j);
        *(float4*)&Qs[r*QP + j] = qv;
    }
    __syncthreads();

    const float ab = abias[hh];
    const int w = tid >> 5, lane = tid & 31;
    const int rowbase = (w >> 1) * 16;   // 0,16,32,48
    const int h = w & 1;
    const int k0l = 64*h + lane, k1l = k0l + 32;

    // PV mapping: 4 outputs/thread (rows qp, qp+32; dims 2dp, 2dp+1)
    const int qp = tid >> 3, dp = tid & 7;
    u64 a00 = 0ull, a01 = 0ull, a10 = 0ull, a11 = 0ull;

    float t0[16], t1[16];

    for (int kt = 0; kt < Nv/KT2; kt++) {
        const int kb = kt*KT2;
        __syncthreads();   // guard all tiles vs previous iteration consumers
        // --- load K (row-major) / V (transposed) tiles: 128 x 16 each ---
        #pragma unroll
        for (int ii = 0; ii < 2; ii++) {
            int id = tid + ii*256;
            int r = id >> 2, j = (id & 3) << 2;
            size_t goff = (size_t)(bb*Nv + kb + r)*Hv + hh*HDv + j;
            float4 kv = *(const float4*)(Kg + goff);
            float* kd = &Ks[r*KP2 + j];
            *(float2*)kd     = make_float2(kv.x, kv.y);
            *(float2*)(kd+2) = make_float2(kv.z, kv.w);
            float4 vv = *(const float4*)(V + goff);
            Vt[(j+0)*VP + r] = vv.x;
            Vt[(j+1)*VP + r] = vv.y;
            Vt[(j+2)*VP + r] = vv.z;
            Vt[(j+3)*VP + r] = vv.w;
        }
        if (tid < KT2) maskt[tid] = mask[bb*Nv + kb + tid];
        __syncthreads();

        // --- scores: 16 rows x 2 keys per lane ---
        u64 kr0[8], kr1[8];
        {
            const u64* p0 = (const u64*)&Ks[k0l*KP2];
            const u64* p1 = (const u64*)&Ks[k1l*KP2];
            #pragma unroll
            for (int d=0; d<8; d++) { kr0[d]=p0[d]; kr1[d]=p1[d]; }
        }
        const bool m0 = (maskt[k0l] != 0), m1 = (maskt[k1l] != 0);
        #pragma unroll
        for (int r = 0; r < 16; r++) {
            const float4* qf = (const float4*)&Qs[(rowbase + r)*QP];
            float4 qv0 = qf[0], qv1 = qf[1], qv2 = qf[2], qv3 = qf[3];
            u64 qd0 = pack2(qv0.x, qv0.y), qd1 = pack2(qv0.z, qv0.w);
            u64 qd2 = pack2(qv1.x, qv1.y), qd3 = pack2(qv1.z, qv1.w);
            u64 qd4 = pack2(qv2.x, qv2.y), qd5 = pack2(qv2.z, qv2.w);
            u64 qd6 = pack2(qv3.x, qv3.y), qd7 = pack2(qv3.z, qv3.w);
            u64 s0p = 0ull, s1p = 0ull;
            fma2(s0p, qd0, kr0[0]); fma2(s1p, qd0, kr1[0]);
            fma2(s0p, qd1, kr0[1]); fma2(s1p, qd1, kr1[1]);
            fma2(s0p, qd2, kr0[2]); fma2(s1p, qd2, kr1[2]);
            fma2(s0p, qd3, kr0[3]); fma2(s1p, qd3, kr1[3]);
            fma2(s0p, qd4, kr0[4]); fma2(s1p, qd4, kr1[4]);
            fma2(s0p, qd5, kr0[5]); fma2(s1p, qd5, kr1[5]);
            fma2(s0p, qd6, kr0[6]); fma2(s1p, qd6, kr1[6]);
            fma2(s0p, qd7, kr0[7]); fma2(s1p, qd7, kr1[7]);
            float e, o;
            unpack2(s0p, e, o); float s0 = (e+o)*0.25f;
            unpack2(s1p, e, o); float s1 = (e+o)*0.25f;
            const unsigned char* brow = bins + (size_t)(q0g + rowbase + r)*Nv + kb;
            s0 = m0 ? -1e9f : (s0 + db[brow[k0l]] + ab);
            s1 = m1 ? -1e9f : (s1 + db[brow[k1l]] + ab);
            t0[r] = s0; t1[r] = s1;
        }
        // --- per-warp-half stats (max + sum of exp) ---
        #pragma unroll
        for (int r = 0; r < 16; r++) {
            float m = fmaxf(t0[r], t1[r]);
            #pragma unroll
            for (int off=16; off; off>>=1)
                m = fmaxf(m, __shfl_xor_sync(0xffffffffu, m, off));
            float e0 = __expf(t0[r] - m);
            float e1 = __expf(t1[r] - m);
            t0[r] = e0; t1[r] = e1;
            float s = e0 + e1;
            #pragma unroll
            for (int off=16; off; off>>=1)
                s += __shfl_xor_sync(0xffffffffu, s, off);
            if (lane == 0) {
                pm[h*QT2 + rowbase + r] = m;
                ps[h*QT2 + rowbase + r] = s;
            }
        }
        __syncthreads();
        // --- combine halves + running stats (one thread per row) ---
        if (tid < QT2) {
            int r = tid;
            float mA = pm[r], mB = pm[QT2 + r];
            float oldm = rowm[r];
            float nm = fmaxf(oldm, fmaxf(mA, mB));
            float so = __expf(oldm - nm);
            float sA = __expf(mA - nm);
            float sB = __expf(mB - nm);
            rowl[r] = rowl[r]*so + ps[r]*sA + ps[QT2 + r]*sB;
            rowm[r] = nm;
            rsc[r]  = so;
            sc0[r]  = sA;
            sc1[r]  = sB;
        }
        __syncthreads();
        // --- write P (scaled to common max) ---
        const float* schalf = h ? sc1 : sc0;
        #pragma unroll
        for (int r = 0; r < 16; r++) {
            float sc = schalf[rowbase + r];
            P[(rowbase + r)*SP2 + k0l] = t0[r]*sc;
            P[(rowbase + r)*SP2 + k1l] = t1[r]*sc;
        }
        __syncthreads();
        // --- PV: rescale accs, then accumulate this tile ---
        {
            u64 r0p = pack2(rsc[qp],    rsc[qp]);
            u64 r1p = pack2(rsc[qp+32], rsc[qp+32]);
            a00 = mul2(a00, r0p); a01 = mul2(a01, r0p);
            a10 = mul2(a10, r1p); a11 = mul2(a11, r1p);
            const u64* p0 = (const u64*)&P[qp*SP2];
            const u64* p1 = (const u64*)&P[(qp+32)*SP2];
            const u64* v0 = (const u64*)&Vt[(2*dp  )*VP];
            const u64* v1 = (const u64*)&Vt[(2*dp+1)*VP];
            #pragma unroll 8
            for (int k2 = 0; k2 < KT2/2; k2++) {
                u64 pa = p0[k2], pb = p1[k2];
                u64 va = v0[k2], vb = v1[k2];
                fma2(a00, pa, va); fma2(a01, pa, vb);
                fma2(a10, pb, va); fma2(a11, pb, vb);
            }
        }
    }
    // --- epilogue ---
    float inv0 = 1.0f / rowl[qp];
    float inv1 = 1.0f / rowl[qp+32];
    float e, o;
    float* out0 = AO + (size_t)(q0g + qp)*Hv + hh*HDv + 2*dp;
    float* out1 = AO + (size_t)(q0g + qp + 32)*Hv + hh*HDv + 2*dp;
    unpack2(a00, e, o); float o00 = (e+o)*inv0;
    unpack2(a01, e, o); float o01 = (e+o)*inv0;
    unpack2(a10, e, o); float o10 = (e+o)*inv1;
    unpack2(a11, e, o); float o11 = (e+o)*inv1;
    *(float2*)out0 = make_float2(o00, o01);
    *(float2*)out1 = make_float2(o10, o11);
}

// ---------------- launch ----------------
extern "C" void kernel_launch(void* const* d_in, const int* in_sizes, int n_in,
                              void* d_out, int out_size)
{
    const float* x    = (const float*)d_in[0];
    const float* dist = (const float*)d_in[1];
    const int*   mask = (const int*)d_in[2];
    const float* Wq  = (const float*)d_in[3];
    const float* bq  = (const float*)d_in[4];
    const float* Wk  = (const float*)d_in[5];
    const float* bk  = (const float*)d_in[6];
    const float* Wv  = (const float*)d_in[7];
    const float* bv  = (const float*)d_in[8];
    const float* Wo  = (const float*)d_in[9];
    const float* bo  = (const float*)d_in[10];
    const float* demb= (const float*)d_in[11];
    const float* ab  = (const float*)d_in[12];
    const float* g1  = (const float*)d_in[13];
    const float* b1  = (const float*)d_in[14];
    const float* g2  = (const float*)d_in[15];
    const float* b2  = (const float*)d_in[16];
    const float* Wf1 = (const float*)d_in[17];
    const float* bf1 = (const float*)d_in[18];
    const float* Wf2 = (const float*)d_in[19];
    const float* bf2 = (const float*)d_in[20];

    float* h = (float*)d_out;
    float *hn, *q, *k, *v, *ao, *u;
    unsigned char* bins;
    cudaGetSymbolAddress((void**)&hn, g_hn);
    cudaGetSymbolAddress((void**)&q,  g_q);
    cudaGetSymbolAddress((void**)&k,  g_k);
    cudaGetSymbolAddress((void**)&v,  g_v);
    cudaGetSymbolAddress((void**)&ao, g_ao);
    cudaGetSymbolAddress((void**)&u,  g_u);
    cudaGetSymbolAddress((void**)&bins, g_bins);

    cudaFuncSetAttribute(attn_kernel,
        cudaFuncAttributeMaxDynamicSharedMemorySize, ATTN_SMEM_BYTES);

    cudaMemcpyAsync(h, x, (size_t)ROWS*Hv*sizeof(float), cudaMemcpyDeviceToDevice);
    bins_kernel<<<(ROWS*Nv)/1024, 256>>>(dist, bins);

    dim3 gqkv(3, ROWS/128);          // fused QKV
    dim3 gone(1, ROWS/128);          // N=128 GEMMs
    dim3 gff1(2*FFv/128, ROWS/128);  // (8, 128)
    dim3 gattn(Nv/QT2, NHv, Bv);     // (8, 8, 32)

    for (int l = 0; l < 3; l++) {
        ln_kernel<<<ROWS/8, 256>>>(h, g1 + l*Hv, b1 + l*Hv, hn);
        gemm_kernel<3><<<gqkv, 256>>>(hn,
            Wq + (size_t)l*Hv*Hv, bq + l*Hv, q,
            Wk + (size_t)l*Hv*Hv, bk + l*Hv, k,
            Wv + (size_t)l*Hv*Hv, bv + l*Hv, v,
            nullptr, Hv, Hv);
        attn_kernel<<<gattn, 256, ATTN_SMEM_BYTES>>>(q, k, v, bins, mask,
                                    demb + (size_t)l*NBINS*NHv, ab + l*NHv, ao);
        gemm_kernel<1><<<gone, 256>>>(ao,
            Wo + (size_t)l*Hv*Hv, bo + l*Hv, h,
            nullptr, nullptr, nullptr, nullptr, nullptr, nullptr,
            h, Hv, Hv);
        ln_kernel<<<ROWS/8, 256>>>(h, g2 + l*Hv, b2 + l*Hv, hn);
        gemm_kernel<0><<<gff1, 256>>>(hn,
            Wf1 + (size_t)l*Hv*2*FFv, bf1 + (size_t)l*2*FFv, u,
            nullptr, nullptr, nullptr, nullptr, nullptr, nullptr,
            nullptr, Hv, 2*FFv);
        gemm_kernel<2><<<gone, 256>>>(u,
            Wf2 + (size_t)l*FFv*Hv, bf2 + l*Hv, h,
            nullptr, nullptr, nullptr, nullptr, nullptr, nullptr,
            h, FFv, Hv);
    }
}

// round 15
// speedup vs baseline: 1.1453x; 1.0171x over previous
#include <cuda_runtime.h>
#include <math.h>

#define Bv 32
#define Nv 512
#define Hv 128
#define NHv 8
#define HDv 16
#define FFv 512
#define NBINS 50
#define ROWS (Bv*Nv)   // 16384

typedef unsigned long long u64;

// ---------------- packed fp32x2 helpers (sm_103a FFMA2 path) ----------------
__device__ __forceinline__ u64 pack2(float x, float y){
    u64 r; asm("mov.b64 %0, {%1, %2};" : "=l"(r) : "f"(x), "f"(y)); return r;
}
__device__ __forceinline__ void unpack2(u64 v, float& x, float& y){
    asm("mov.b64 {%0, %1}, %2;" : "=f"(x), "=f"(y) : "l"(v));
}
__device__ __forceinline__ void fma2(u64& c, u64 a, u64 b){
    asm("fma.rn.f32x2 %0, %1, %2, %3;" : "=l"(c) : "l"(a), "l"(b), "l"(c));
}
__device__ __forceinline__ u64 mul2(u64 a, u64 b){
    u64 r; asm("mul.rn.f32x2 %0, %1, %2;" : "=l"(r) : "l"(a), "l"(b)); return r;
}

// ---------------- scratch (no allocations allowed) ----------------
__device__ float g_hn[ROWS*Hv];
__device__ float g_q [ROWS*Hv];
__device__ float g_k [ROWS*Hv];
__device__ float g_v [ROWS*Hv];
__device__ float g_ao[ROWS*Hv];
__device__ float g_u [ROWS*2*FFv];
__device__ unsigned char g_bins[(size_t)ROWS*Nv];   // 8.4 MB, fits L2

// ---------------- distance->bin precompute (once per launch) ----------------
__global__ __launch_bounds__(256) void bins_kernel(
    const float* __restrict__ dist, unsigned char* __restrict__ bins)
{
    int i = (blockIdx.x*256 + threadIdx.x) * 4;
    float4 d = *(const float4*)(dist + i);
    int b0 = (int)(d.x*10.f); b0 = b0<0?0:(b0>NBINS-1?NBINS-1:b0);
    int b1 = (int)(d.y*10.f); b1 = b1<0?0:(b1>NBINS-1?NBINS-1:b1);
    int b2 = (int)(d.z*10.f); b2 = b2<0?0:(b2>NBINS-1?NBINS-1:b2);
    int b3 = (int)(d.w*10.f); b3 = b3<0?0:(b3>NBINS-1?NBINS-1:b3);
    uchar4 o; o.x=(unsigned char)b0; o.y=(unsigned char)b1;
    o.z=(unsigned char)b2; o.w=(unsigned char)b3;
    *(uchar4*)(bins + i) = o;
}

// ---------------- LayerNorm: one warp per 128-wide row (used once) ----------
__global__ __launch_bounds__(256) void ln_kernel(
    const float* __restrict__ h,
    const float* __restrict__ gamma,
    const float* __restrict__ beta,
    float* __restrict__ out)
{
    int row  = blockIdx.x * 8 + (threadIdx.x >> 5);
    int lane = threadIdx.x & 31;
    const float4* hp = (const float4*)(h + (size_t)row * Hv);
    float4 v = hp[lane];
    float s  = v.x + v.y + v.z + v.w;
    float ss = v.x*v.x + v.y*v.y + v.z*v.z + v.w*v.w;
    #pragma unroll
    for (int off = 16; off; off >>= 1) {
        s  += __shfl_xor_sync(0xffffffffu, s,  off);
        ss += __shfl_xor_sync(0xffffffffu, ss, off);
    }
    float mu  = s * (1.0f/Hv);
    float var = ss * (1.0f/Hv) - mu*mu;
    float inv = rsqrtf(var + 1e-5f);
    float4 g4 = ((const float4*)gamma)[lane];
    float4 b4 = ((const float4*)beta)[lane];
    float4 o;
    o.x = (v.x-mu)*inv*g4.x + b4.x;
    o.y = (v.y-mu)*inv*g4.y + b4.y;
    o.z = (v.z-mu)*inv*g4.z + b4.z;
    o.w = (v.w-mu)*inv*g4.w + b4.w;
    ((float4*)(out + (size_t)row*Hv))[lane] = o;
}

// ---------------- SGEMM: 128x128 tile, BK=16, 8x8 micro-tile, f32x2 FMA ----
// MODE: 0 = plain, 1 = +residual, 2 = GLU(A)+residual, 3 = fused QKV (3 W/b/C)
// LNF: fused LayerNorm epilogue (requires Nc=128, bn=0; writes HN=LN(C row))
template<int MODE, bool LNF>
__global__ __launch_bounds__(256) void gemm_kernel(
    const float* __restrict__ A,
    const float* __restrict__ W0, const float* __restrict__ B0, float* __restrict__ C0,
    const float* __restrict__ W1, const float* __restrict__ B1c, float* __restrict__ C1,
    const float* __restrict__ W2, const float* __restrict__ B2c, float* __restrict__ C2,
    const float* __restrict__ R, int K, int Nc,
    const float* __restrict__ lng, const float* __restrict__ lnb,
    float* __restrict__ HN)
{
    // smem: mainloop uses As[2][16][132] (4224) + Ws[2][16][128] (4096) = 8320.
    // LNF epilogue reuses: redS[2048], redQ[2048], mu[128], inv[128] = 4352.
    __shared__ __align__(16) float smbuf[8320];
    float (*As)[16][132] = (float(*)[16][132])smbuf;
    float (*Ws)[16][128] = (float(*)[16][128])(smbuf + 4224);

    const int tid = threadIdx.x;
    const float *W, *bias; float* C;
    int bn;
    if (MODE == 3) {
        int s = blockIdx.x;
        W    = (s==0)?W0:((s==1)?W1:W2);
        bias = (s==0)?B0:((s==1)?B1c:B2c);
        C    = (s==0)?C0:((s==1)?C1:C2);
        bn = 0;
    } else { W = W0; bias = B0; C = C0; bn = blockIdx.x * 128; }
    const int bm = blockIdx.y * 128;
    const int tx = tid & 15, ty = tid >> 4;
    const int ar = tid >> 1, ac = (tid & 1) * 8;   // A loader: row ar, 8 cols
    const int wr = tid >> 4, wc = (tid & 15) * 8;  // W loader: row wr, 8 cols
    const int ldA = (MODE==2) ? (2*FFv) : K;
    const float* Arow = A + (size_t)(bm + ar) * ldA;
    const float* Wp   = W + (size_t)wr * Nc + bn + wc;

    u64 acc[8][4];
    #pragma unroll
    for (int i=0;i<8;i++)
        #pragma unroll
        for (int j=0;j<4;j++) acc[i][j] = 0ull;

    float4 a0v, a1v, w0v, w1v;
    #define LOADT(k0) do { \
        if (MODE==2) { \
            float4 p0 = *(const float4*)(Arow + (k0) + ac); \
            float4 p1 = *(const float4*)(Arow + (k0) + ac + 4); \
            float4 s0 = *(const float4*)(Arow + FFv + (k0) + ac); \
            float4 s1 = *(const float4*)(Arow + FFv + (k0) + ac + 4); \
            a0v.x = p0.x/(1.f+__expf(-s0.x)); a0v.y = p0.y/(1.f+__expf(-s0.y)); \
            a0v.z = p0.z/(1.f+__expf(-s0.z)); a0v.w = p0.w/(1.f+__expf(-s0.w)); \
            a1v.x = p1.x/(1.f+__expf(-s1.x)); a1v.y = p1.y/(1.f+__expf(-s1.y)); \
            a1v.z = p1.z/(1.f+__expf(-s1.z)); a1v.w = p1.w/(1.f+__expf(-s1.w)); \
        } else { \
            a0v = *(const float4*)(Arow + (k0) + ac); \
            a1v = *(const float4*)(Arow + (k0) + ac + 4); \
        } \
        w0v = *(const float4*)(Wp + (size_t)(k0)*Nc); \
        w1v = *(const float4*)(Wp + (size_t)(k0)*Nc + 4); \
    } while(0)
    #define STORET(b) do { \
        As[b][ac+0][ar]=a0v.x; As[b][ac+1][ar]=a0v.y; \
        As[b][ac+2][ar]=a0v.z; As[b][ac+3][ar]=a0v.w; \
        As[b][ac+4][ar]=a1v.x; As[b][ac+5][ar]=a1v.y; \
        As[b][ac+6][ar]=a1v.z; As[b][ac+7][ar]=a1v.w; \
        *(float4*)&Ws[b][wr][wc]   = w0v; \
        *(float4*)&Ws[b][wr][wc+4] = w1v; \
    } while(0)

    LOADT(0); STORET(0); __syncthreads();
    const int nt = K/16;
    for (int t = 0; t < nt; t++) {
        int cur = t & 1;
        if (t+1 < nt) LOADT((t+1)*16);
        #pragma unroll
        for (int kk = 0; kk < 16; kk++) {
            float4 af0 = *(float4*)&As[cur][kk][ty*8];
            float4 af1 = *(float4*)&As[cur][kk][ty*8+4];
            const u64* bp = (const u64*)&Ws[cur][kk][tx*8];
            u64 b2[4]; b2[0]=bp[0]; b2[1]=bp[1]; b2[2]=bp[2]; b2[3]=bp[3];
            u64 as2[8];
            as2[0]=pack2(af0.x,af0.x); as2[1]=pack2(af0.y,af0.y);
            as2[2]=pack2(af0.z,af0.z); as2[3]=pack2(af0.w,af0.w);
            as2[4]=pack2(af1.x,af1.x); as2[5]=pack2(af1.y,af1.y);
            as2[6]=pack2(af1.z,af1.z); as2[7]=pack2(af1.w,af1.w);
            #pragma unroll
            for (int i=0;i<8;i++)
                #pragma unroll
                for (int j=0;j<4;j++) fma2(acc[i][j], as2[i], b2[j]);
        }
        if (t+1 < nt) STORET(cur^1);
        __syncthreads();
    }
    #undef LOADT
    #undef STORET

    const int cn = bn + tx*8;
    float4 bv0 = *(const float4*)(bias + cn);
    float4 bv1 = *(const float4*)(bias + cn + 4);
    float c[8][8];
    #pragma unroll
    for (int i = 0; i < 8; i++) {
        int cm = bm + ty*8 + i;
        #pragma unroll
        for (int j=0;j<4;j++) unpack2(acc[i][j], c[i][2*j], c[i][2*j+1]);
        c[i][0]+=bv0.x; c[i][1]+=bv0.y; c[i][2]+=bv0.z; c[i][3]+=bv0.w;
        c[i][4]+=bv1.x; c[i][5]+=bv1.y; c[i][6]+=bv1.z; c[i][7]+=bv1.w;
        if (MODE==1 || MODE==2) {
            float4 r0 = *(const float4*)(R + (size_t)cm*Nc + cn);
            float4 r1 = *(const float4*)(R + (size_t)cm*Nc + cn + 4);
            c[i][0]+=r0.x; c[i][1]+=r0.y; c[i][2]+=r0.z; c[i][3]+=r0.w;
            c[i][4]+=r1.x; c[i][5]+=r1.y; c[i][6]+=r1.z; c[i][7]+=r1.w;
        }
        *(float4*)(C + (size_t)cm*Nc + cn)     = make_float4(c[i][0],c[i][1],c[i][2],c[i][3]);
        *(float4*)(C + (size_t)cm*Nc + cn + 4) = make_float4(c[i][4],c[i][5],c[i][6],c[i][7]);
    }

    if (LNF) {
        // Fused LayerNorm over the just-computed rows (Nc==128, bn==0).
        float* redS = smbuf;          // [128][16]
        float* redQ = smbuf + 2048;   // [128][16]
        float* muA  = smbuf + 4096;   // [128]
        float* invA = smbuf + 4224;   // [128]
        // mainloop's final __syncthreads guarantees As/Ws no longer read
        #pragma unroll
        for (int i = 0; i < 8; i++) {
            float s = 0.f, q = 0.f;
            #pragma unroll
            for (int j = 0; j < 8; j++) { s += c[i][j]; q += c[i][j]*c[i][j]; }
            redS[(ty*8+i)*16 + tx] = s;
            redQ[(ty*8+i)*16 + tx] = q;
        }
        __syncthreads();
        if (tid < 128) {
            float s = 0.f, q = 0.f;
            #pragma unroll
            for (int t = 0; t < 16; t++) { s += redS[tid*16+t]; q += redQ[tid*16+t]; }
            float mu = s * (1.0f/Hv);
            float var = q * (1.0f/Hv) - mu*mu;
            muA[tid]  = mu;
            invA[tid] = rsqrtf(var + 1e-5f);
        }
        __syncthreads();
        float4 g0 = *(const float4*)(lng + cn);
        float4 g1_ = *(const float4*)(lng + cn + 4);
        float4 bb0 = *(const float4*)(lnb + cn);
        float4 bb1 = *(const float4*)(lnb + cn + 4);
        #pragma unroll
        for (int i = 0; i < 8; i++) {
            int row = ty*8 + i;
            int cm = bm + row;
            float mu = muA[row], inv = invA[row];
            float4 o0, o1;
            o0.x = (c[i][0]-mu)*inv*g0.x + bb0.x;
            o0.y = (c[i][1]-mu)*inv*g0.y + bb0.y;
            o0.z = (c[i][2]-mu)*inv*g0.z + bb0.z;
            o0.w = (c[i][3]-mu)*inv*g0.w + bb0.w;
            o1.x = (c[i][4]-mu)*inv*g1_.x + bb1.x;
            o1.y = (c[i][5]-mu)*inv*g1_.y + bb1.y;
            o1.z = (c[i][6]-mu)*inv*g1_.z + bb1.z;
            o1.w = (c[i][7]-mu)*inv*g1_.w + bb1.w;
            *(float4*)(HN + (size_t)cm*Hv + cn)     = o0;
            *(float4*)(HN + (size_t)cm*Hv + cn + 4) = o1;
        }
    }
}

// ---------------- fused attention v2.3 (unchanged from R13 best) ------------
#define QT2 64
#define KT2 128
#define QP 20
#define KP2 18
#define VP 134
#define SP2 132

#define SM_QS   0
#define SM_KS   (SM_QS + QT2*QP)        // 1280
#define SM_VT   (SM_KS + KT2*KP2)       // +2304
#define SM_P    (SM_VT + HDv*VP)        // +2144
#define SM_PM   (SM_P  + QT2*SP2)       // +8448
#define SM_PS   (SM_PM + 2*QT2)
#define SM_RM   (SM_PS + 2*QT2)
#define SM_RL   (SM_RM + QT2)
#define SM_RS   (SM_RL + QT2)
#define SM_SC0  (SM_RS + QT2)
#define SM_SC1  (SM_SC0 + QT2)
#define SM_DB   (SM_SC1 + QT2)
#define SM_MASK (SM_DB + 64)
#define ATTN_SMEM_FLOATS (SM_MASK + KT2)
#define ATTN_SMEM_BYTES  (ATTN_SMEM_FLOATS*4)

__global__ __launch_bounds__(256) void attn_kernel(
    const float* __restrict__ Q, const float* __restrict__ Kg,
    const float* __restrict__ V, const unsigned char* __restrict__ bins,
    const int* __restrict__ mask,
    const float* __restrict__ demb, const float* __restrict__ abias,
    float* __restrict__ AO)
{
    extern __shared__ __align__(16) float sm[];
    float* Qs = sm + SM_QS;
    float* Ks = sm + SM_KS;
    float* Vt = sm + SM_VT;
    float* P  = sm + SM_P;
    float* pm = sm + SM_PM;
    float* ps = sm + SM_PS;
    float* rowm = sm + SM_RM;
    float* rowl = sm + SM_RL;
    float* rsc  = sm + SM_RS;
    float* sc0  = sm + SM_SC0;
    float* sc1  = sm + SM_SC1;
    float* db   = sm + SM_DB;
    int*  maskt = (int*)(sm + SM_MASK);

    const int tid = threadIdx.x;
    const int qt = blockIdx.x, hh = blockIdx.y, bb = blockIdx.z;
    const int q0g = bb*Nv + qt*QT2;

    if (tid < NBINS) db[tid] = demb[tid*NHv + hh];
    if (tid < QT2) { rowm[tid] = -1e30f; rowl[tid] = 0.f; }
    {   // load Q tile [64 x 16] (QP=20: float4-aligned rows)
        int r = tid >> 2, j = (tid & 3) << 2;
        float4 qv = *(const float4*)(Q + (size_t)(q0g + r)*Hv + hh*HDv + j);
        *(float4*)&Qs[r*QP + j] = qv;
    }
    __syncthreads();

    const float ab = abias[hh];
    const int w = tid >> 5, lane = tid & 31;
    const int rowbase = (w >> 1) * 16;   // 0,16,32,48
    const int h = w & 1;
    const int k0l = 64*h + lane, k1l = k0l + 32;

    const int qp = tid >> 3, dp = tid & 7;
    u64 a00 = 0ull, a01 = 0ull, a10 = 0ull, a11 = 0ull;

    float t0[16], t1[16];

    for (int kt = 0; kt < Nv/KT2; kt++) {
        const int kb = kt*KT2;
        __syncthreads();
        #pragma unroll
        for (int ii = 0; ii < 2; ii++) {
            int id = tid + ii*256;
            int r = id >> 2, j = (id & 3) << 2;
            size_t goff = (size_t)(bb*Nv + kb + r)*Hv + hh*HDv + j;
            float4 kv = *(const float4*)(Kg + goff);
            float* kd = &Ks[r*KP2 + j];
            *(float2*)kd     = make_float2(kv.x, kv.y);
            *(float2*)(kd+2) = make_float2(kv.z, kv.w);
            float4 vv = *(const float4*)(V + goff);
            Vt[(j+0)*VP + r] = vv.x;
            Vt[(j+1)*VP + r] = vv.y;
            Vt[(j+2)*VP + r] = vv.z;
            Vt[(j+3)*VP + r] = vv.w;
        }
        if (tid < KT2) maskt[tid] = mask[bb*Nv + kb + tid];
        __syncthreads();

        u64 kr0[8], kr1[8];
        {
            const u64* p0 = (const u64*)&Ks[k0l*KP2];
            const u64* p1 = (const u64*)&Ks[k1l*KP2];
            #pragma unroll
            for (int d=0; d<8; d++) { kr0[d]=p0[d]; kr1[d]=p1[d]; }
        }
        const bool m0 = (maskt[k0l] != 0), m1 = (maskt[k1l] != 0);
        #pragma unroll
        for (int r = 0; r < 16; r++) {
            const float4* qf = (const float4*)&Qs[(rowbase + r)*QP];
            float4 qv0 = qf[0], qv1 = qf[1], qv2 = qf[2], qv3 = qf[3];
            u64 qd0 = pack2(qv0.x, qv0.y), qd1 = pack2(qv0.z, qv0.w);
            u64 qd2 = pack2(qv1.x, qv1.y), qd3 = pack2(qv1.z, qv1.w);
            u64 qd4 = pack2(qv2.x, qv2.y), qd5 = pack2(qv2.z, qv2.w);
            u64 qd6 = pack2(qv3.x, qv3.y), qd7 = pack2(qv3.z, qv3.w);
            u64 s0p = 0ull, s1p = 0ull;
            fma2(s0p, qd0, kr0[0]); fma2(s1p, qd0, kr1[0]);
            fma2(s0p, qd1, kr0[1]); fma2(s1p, qd1, kr1[1]);
            fma2(s0p, qd2, kr0[2]); fma2(s1p, qd2, kr1[2]);
            fma2(s0p, qd3, kr0[3]); fma2(s1p, qd3, kr1[3]);
            fma2(s0p, qd4, kr0[4]); fma2(s1p, qd4, kr1[4]);
            fma2(s0p, qd5, kr0[5]); fma2(s1p, qd5, kr1[5]);
            fma2(s0p, qd6, kr0[6]); fma2(s1p, qd6, kr1[6]);
            fma2(s0p, qd7, kr0[7]); fma2(s1p, qd7, kr1[7]);
            float e, o;
            unpack2(s0p, e, o); float s0 = (e+o)*0.25f;
            unpack2(s1p, e, o); float s1 = (e+o)*0.25f;
            const unsigned char* brow = bins + (size_t)(q0g + rowbase + r)*Nv + kb;
            s0 = m0 ? -1e9f : (s0 + db[brow[k0l]] + ab);
            s1 = m1 ? -1e9f : (s1 + db[brow[k1l]] + ab);
            t0[r] = s0; t1[r] = s1;
        }
        #pragma unroll
        for (int r = 0; r < 16; r++) {
            float m = fmaxf(t0[r], t1[r]);
            #pragma unroll
            for (int off=16; off; off>>=1)
                m = fmaxf(m, __shfl_xor_sync(0xffffffffu, m, off));
            float e0 = __expf(t0[r] - m);
            float e1 = __expf(t1[r] - m);
            t0[r] = e0; t1[r] = e1;
            float s = e0 + e1;
            #pragma unroll
            for (int off=16; off; off>>=1)
                s += __shfl_xor_sync(0xffffffffu, s, off);
            if (lane == 0) {
                pm[h*QT2 + rowbase + r] = m;
                ps[h*QT2 + rowbase + r] = s;
            }
        }
        __syncthreads();
        if (tid < QT2) {
            int r = tid;
            float mA = pm[r], mB = pm[QT2 + r];
            float oldm = rowm[r];
            float nm = fmaxf(oldm, fmaxf(mA, mB));
            float so = __expf(oldm - nm);
            float sA = __expf(mA - nm);
            float sB = __expf(mB - nm);
            rowl[r] = rowl[r]*so + ps[r]*sA + ps[QT2 + r]*sB;
            rowm[r] = nm;
            rsc[r]  = so;
            sc0[r]  = sA;
            sc1[r]  = sB;
        }
        __syncthreads();
        const float* schalf = h ? sc1 : sc0;
        #pragma unroll
        for (int r = 0; r < 16; r++) {
            float sc = schalf[rowbase + r];
            P[(rowbase + r)*SP2 + k0l] = t0[r]*sc;
            P[(rowbase + r)*SP2 + k1l] = t1[r]*sc;
        }
        __syncthreads();
        {
            u64 r0p = pack2(rsc[qp],    rsc[qp]);
            u64 r1p = pack2(rsc[qp+32], rsc[qp+32]);
            a00 = mul2(a00, r0p); a01 = mul2(a01, r0p);
            a10 = mul2(a10, r1p); a11 = mul2(a11, r1p);
            const u64* p0 = (const u64*)&P[qp*SP2];
            const u64* p1 = (const u64*)&P[(qp+32)*SP2];
            const u64* v0 = (const u64*)&Vt[(2*dp  )*VP];
            const u64* v1 = (const u64*)&Vt[(2*dp+1)*VP];
            #pragma unroll 8
            for (int k2 = 0; k2 < KT2/2; k2++) {
                u64 pa = p0[k2], pb = p1[k2];
                u64 va = v0[k2], vb = v1[k2];
                fma2(a00, pa, va); fma2(a01, pa, vb);
                fma2(a10, pb, va); fma2(a11, pb, vb);
            }
        }
    }
    float inv0 = 1.0f / rowl[qp];
    float inv1 = 1.0f / rowl[qp+32];
    float e, o;
    float* out0 = AO + (size_t)(q0g + qp)*Hv + hh*HDv + 2*dp;
    float* out1 = AO + (size_t)(q0g + qp + 32)*Hv + hh*HDv + 2*dp;
    unpack2(a00, e, o); float o00 = (e+o)*inv0;
    unpack2(a01, e, o); float o01 = (e+o)*inv0;
    unpack2(a10, e, o); float o10 = (e+o)*inv1;
    unpack2(a11, e, o); float o11 = (e+o)*inv1;
    *(float2*)out0 = make_float2(o00, o01);
    *(float2*)out1 = make_float2(o10, o11);
}

// ---------------- launch ----------------
extern "C" void kernel_launch(void* const* d_in, const int* in_sizes, int n_in,
                              void* d_out, int out_size)
{
    const float* x    = (const float*)d_in[0];
    const float* dist = (const float*)d_in[1];
    const int*   mask = (const int*)d_in[2];
    const float* Wq  = (const float*)d_in[3];
    const float* bq  = (const float*)d_in[4];
    const float* Wk  = (const float*)d_in[5];
    const float* bk  = (const float*)d_in[6];
    const float* Wv  = (const float*)d_in[7];
    const float* bv  = (const float*)d_in[8];
    const float* Wo  = (const float*)d_in[9];
    const float* bo  = (const float*)d_in[10];
    const float* demb= (const float*)d_in[11];
    const float* ab  = (const float*)d_in[12];
    const float* g1  = (const float*)d_in[13];
    const float* b1  = (const float*)d_in[14];
    const float* g2  = (const float*)d_in[15];
    const float* b2  = (const float*)d_in[16];
    const float* Wf1 = (const float*)d_in[17];
    const float* bf1 = (const float*)d_in[18];
    const float* Wf2 = (const float*)d_in[19];
    const float* bf2 = (const float*)d_in[20];

    float* h = (float*)d_out;
    float *hn, *q, *k, *v, *ao, *u;
    unsigned char* bins;
    cudaGetSymbolAddress((void**)&hn, g_hn);
    cudaGetSymbolAddress((void**)&q,  g_q);
    cudaGetSymbolAddress((void**)&k,  g_k);
    cudaGetSymbolAddress((void**)&v,  g_v);
    cudaGetSymbolAddress((void**)&ao, g_ao);
    cudaGetSymbolAddress((void**)&u,  g_u);
    cudaGetSymbolAddress((void**)&bins, g_bins);

    cudaFuncSetAttribute(attn_kernel,
        cudaFuncAttributeMaxDynamicSharedMemorySize, ATTN_SMEM_BYTES);

    bins_kernel<<<(ROWS*Nv)/1024, 256>>>(dist, bins);

    dim3 gqkv(3, ROWS/128);          // fused QKV
    dim3 gone(1, ROWS/128);          // N=128 GEMMs
    dim3 gff1(2*FFv/128, ROWS/128);  // (8, 128)
    dim3 gattn(Nv/QT2, NHv, Bv);     // (8, 8, 32)

    // layer 0 first LN reads x directly (h = d_out not yet initialized;
    // it is fully written by the first gemm<1> epilogue below)
    ln_kernel<<<ROWS/8, 256>>>(x, g1, b1, hn);

    for (int l = 0; l < 3; l++) {
        gemm_kernel<3,false><<<gqkv, 256>>>(hn,
            Wq + (size_t)l*Hv*Hv, bq + l*Hv, q,
            Wk + (size_t)l*Hv*Hv, bk + l*Hv, k,
            Wv + (size_t)l*Hv*Hv, bv + l*Hv, v,
            nullptr, Hv, Hv, nullptr, nullptr, nullptr);
        attn_kernel<<<gattn, 256, ATTN_SMEM_BYTES>>>(q, k, v, bins, mask,
                                    demb + (size_t)l*NBINS*NHv, ab + l*NHv, ao);
        // Wo + residual + fused LN(g2,b2) -> hn (for FF block)
        gemm_kernel<1,true><<<gone, 256>>>(ao,
            Wo + (size_t)l*Hv*Hv, bo + l*Hv, h,
            nullptr, nullptr, nullptr, nullptr, nullptr, nullptr,
            (l==0) ? x : h, Hv, Hv,
            g2 + l*Hv, b2 + l*Hv, hn);
        gemm_kernel<0,false><<<gff1, 256>>>(hn,
            Wf1 + (size_t)l*Hv*2*FFv, bf1 + (size_t)l*2*FFv, u,
            nullptr, nullptr, nullptr, nullptr, nullptr, nullptr,
            nullptr, Hv, 2*FFv, nullptr, nullptr, nullptr);
        if (l < 2) {
            // FF2 + residual + fused LN(next layer g1,b1) -> hn
            gemm_kernel<2,true><<<gone, 256>>>(u,
                Wf2 + (size_t)l*FFv*Hv, bf2 + l*Hv, h,
                nullptr, nullptr, nullptr, nullptr, nullptr, nullptr,
                h, FFv, Hv,
                g1 + (l+1)*Hv, b1 + (l+1)*Hv, hn);
        } else {
            gemm_kernel<2,false><<<gone, 256>>>(u,
                Wf2 + (size_t)l*FFv*Hv, bf2 + l*Hv, h,
                nullptr, nullptr, nullptr, nullptr, nullptr, nullptr,
                h, FFv, Hv, nullptr, nullptr, nullptr);
        }
    }
}